// round 7
// baseline (speedup 1.0000x reference)
#include <cuda_runtime.h>
#include <cstdint>

// PEPS 6x6, D=3, B=16 — quadrant decomposition, cluster of 4 CTAs per config.
// rank 0=TL, 1=TR, 2=BL, 3=BR (bottom/right mirrored so all quadrants run
// identical code). Each quadrant contracts its 9 sites locally (8 steps);
// state = 243 float4 groups. Merge via point-to-point mbarriers (no full
// cluster barriers on the critical path): rank1 -> rank0 (S0 ready),
// rank3 -> rank2, rank2 pushes M2 into rank0 and arrives; done back-edges
// let producers exit safely. Gather loads only the 441 live T entries
// (edge bonds fixed to 0); rest of At zero-filled.

#define NTH 256
#define ATF 108

__device__ __forceinline__ float dot3(float4 a, float4 b) {
    return a.x * b.x + a.y * b.y + a.z * b.z;
}

__device__ __forceinline__ uint32_t smem_u32(const void* p) {
    uint32_t a;
    asm("{ .reg .u64 t; cvta.to.shared.u64 t, %1; cvt.u32.u64 %0, t; }"
        : "=r"(a) : "l"(p));
    return a;
}

__device__ __forceinline__ float ld_cluster_f32(uint32_t laddr, uint32_t rank) {
    uint32_t r; float v;
    asm volatile("mapa.shared::cluster.u32 %0, %1, %2;" : "=r"(r) : "r"(laddr), "r"(rank));
    asm volatile("ld.shared::cluster.f32 %0, [%1];" : "=f"(v) : "r"(r) : "memory");
    return v;
}

__device__ __forceinline__ void st_cluster_f32(uint32_t laddr, uint32_t rank, float v) {
    uint32_t r;
    asm volatile("mapa.shared::cluster.u32 %0, %1, %2;" : "=r"(r) : "r"(laddr), "r"(rank));
    asm volatile("st.shared::cluster.f32 [%0], %1;" :: "r"(r), "f"(v) : "memory");
}

__device__ __forceinline__ void mbar_init(uint32_t addr, uint32_t cnt) {
    asm volatile("mbarrier.init.shared.b64 [%0], %1;" :: "r"(addr), "r"(cnt) : "memory");
}

// arrive on peer CTA's mbarrier (same SMEM offset)
__device__ __forceinline__ void mbar_arrive_remote(uint32_t laddr, uint32_t rank) {
    asm volatile(
        "{ .reg .b32 ra;\n\t"
        "  mapa.shared::cluster.u32 ra, %0, %1;\n\t"
        "  mbarrier.arrive.shared::cluster.b64 _, [ra]; }"
        :: "r"(laddr), "r"(rank) : "memory");
}

// wait phase-0 on own mbarrier
__device__ __forceinline__ void mbar_wait0(uint32_t addr) {
    uint32_t done = 0;
    while (!done) {
        asm volatile(
            "{ .reg .pred p;\n\t"
            "  mbarrier.try_wait.parity.shared.b64 p, [%1], %2, 0x989680;\n\t"
            "  selp.b32 %0, 1, 0, p; }"
            : "=r"(done) : "r"(addr), "r"(0u) : "memory");
    }
}

#define FENCE_CLUSTER() asm volatile("fence.acq_rel.cluster;" ::: "memory")

#define CLUSTER_BAR() do { \
    asm volatile("barrier.cluster.arrive.aligned;" ::: "memory"); \
    asm volatile("barrier.cluster.wait.aligned;"   ::: "memory"); \
} while (0)

__global__ __launch_bounds__(NTH, 1) __cluster_dims__(4, 1, 1)
void peps_quad_kernel(const int* __restrict__ xcfg,
                      const float* __restrict__ T,
                      float* __restrict__ out) {
    __shared__ float4 S0[243];
    __shared__ float4 S1[243];
    __shared__ float  At[9 * ATF];
    __shared__ float  M[729];
    __shared__ float  M2[729];
    __shared__ int    spins[36];
    __shared__ int    sOff[36];
    __shared__ float  red[8];
    __shared__ uint64_t mb_ready, mb_m2, mb_done;

    const int t = threadIdx.x;
    const int b = blockIdx.x >> 2;
    uint32_t rank;
    asm("mov.u32 %0, %%cluster_ctarank;" : "=r"(rank));
    const int bottom = (int)(rank >> 1);
    const int right  = (int)(rank & 1);

    const uint32_t a_ready = smem_u32(&mb_ready);
    const uint32_t a_m2    = smem_u32(&mb_m2);
    const uint32_t a_done  = smem_u32(&mb_done);

    if (t < 36) spins[t] = xcfg[b * 36 + t];
    // zero At (gather only writes live entries)
    {
        float4* Az = (float4*)At;
        for (int i = t; i < 243; i += NTH) Az[i] = make_float4(0.f, 0.f, 0.f, 0.f);
    }
    if (t == 0) { mbar_init(a_ready, 1); mbar_init(a_m2, 1); mbar_init(a_done, 1); }
    __syncthreads();
    CLUSTER_BAR();    // orders mbarrier init before any remote arrive; absorbs skew

    if (t < 36) {
        int xx = t / 6, yy = t % 6;
        int p  = spins[t];
        int pu = (xx > 0) ? spins[t - 6] : 0;
        int pd = (xx < 5) ? spins[t + 6] : 0;
        int pl = (yy > 0) ? spins[t - 1] : 0;
        int pr = (yy < 5) ? spins[t + 1] : 0;
        sOff[t] = (((p * 2 + pu) * 2 + pd) * 2 + pl) * 2 + pr;
    }
    __syncthreads();

    // Sparse gather: only live entries. Site s=qr*3+qc: vertical-in bond a is
    // an edge iff qr==0 (a=0 only); moving-in lane ln is an edge iff qc==0.
    // cumulative live counts: {9,27,27,27,81,81,27,81,81}
    {
        const int cum[10] = {0, 9, 36, 63, 90, 171, 252, 279, 360, 441};
        for (int i = t; i < 441; i += NTH) {
            int s = 0;
            while (i >= cum[s + 1]) ++s;
            int r  = i - cum[s];
            int qr = s / 3, qc = s % 3;
            int na = (qr == 0) ? 1 : 3;
            int nl = (qc == 0) ? 1 : 3;
            int ln = r % nl;  r /= nl;
            int a  = r % na;  r /= na;
            int hp = r % 3;
            int o  = r / 3;
            int x = bottom ? 5 - qr : qr;
            int y = right  ? 5 - qc : qc;
            int u  = bottom ? o : a;
            int d  = bottom ? a : o;
            int l  = right ? hp : ln;
            int rr = right ? ln : hp;
            int site = x * 6 + y;
            At[s * ATF + o * 36 + hp * 12 + a * 4 + ln] =
                T[site * 2592 + (((u * 3 + d) * 3 + l) * 3 + rr) * 32 + sOff[site]];
        }
    }
    __syncthreads();

    // Init = state after site 0: digit a0 (stride 81) = vertical out, lanes = hp.
    if (t < 243) {
        float4 v = make_float4(0.0f, 0.0f, 0.0f, 0.0f);
        if (t == 0 || t == 81 || t == 162) {
            int a0 = t / 81;
            v = make_float4(At[a0 * 36], At[a0 * 36 + 12], At[a0 * 36 + 24], 0.0f);
        }
        S0[t] = v;
    }
    __syncthreads();

    const float4* Atv = (const float4*)At;

#define STEPL(SITE, S3, RD, WR) { \
    if (t < 243) { \
        int d_   = (t / (S3)) % 3; \
        int base = t - d_ * (S3); \
        float4 c0 = (RD)[base]; \
        float4 c1 = (RD)[base + (S3)]; \
        float4 c2 = (RD)[base + 2 * (S3)]; \
        const float4* Av = Atv + (SITE) * 27 + d_ * 9; \
        float r0 = dot3(c0, Av[0]) + dot3(c1, Av[1]) + dot3(c2, Av[2]); \
        float r1 = dot3(c0, Av[3]) + dot3(c1, Av[4]) + dot3(c2, Av[5]); \
        float r2 = dot3(c0, Av[6]) + dot3(c1, Av[7]) + dot3(c2, Av[8]); \
        (WR)[t] = make_float4(r0, r1, r2, 0.0f); \
    } \
    __syncthreads(); \
}

#define STEPC3(SITE, RD, WR) { \
    if (t < 243) { \
        int rr_  = t % 27; \
        int d_   = rr_ / 9; \
        int r_   = (rr_ / 3) % 3; \
        int base = (t / 27) * 27 + (rr_ % 3); \
        const float4* Av = Atv + (SITE) * 27 + d_ * 9 + r_ * 3; \
        float s_ = dot3((RD)[base], Av[0]) + dot3((RD)[base + 9], Av[1]) \
                 + dot3((RD)[base + 18], Av[2]); \
        (WR)[t] = make_float4(s_, 0.0f, 0.0f, 0.0f); \
    } \
    __syncthreads(); \
}

#define STEPC4(SITE, RD, WR) { \
    if (t < 243) { \
        int d_   = (t / 9) % 3; \
        int r_   = t % 3; \
        int base = (t / 27) * 27 + ((t / 3) % 3) * 3; \
        const float4* Av = Atv + (SITE) * 27 + d_ * 9 + r_ * 3; \
        float s_ = dot3((RD)[base], Av[0]) + dot3((RD)[base + 9], Av[1]) \
                 + dot3((RD)[base + 18], Av[2]); \
        (WR)[t] = make_float4(s_, 0.0f, 0.0f, 0.0f); \
    } \
    __syncthreads(); \
}

    STEPL (1, 27, S0, S1)
    STEPC3(2,     S1, S0)
    STEPL (3, 81, S0, S1)
    STEPL (4, 27, S1, S0)
    STEPC4(5,     S0, S1)
    STEPL (6, 81, S1, S0)
    STEPL (7, 27, S0, S1)
    STEPL (8,  9, S1, S0)   // final state in S0
#undef STEPL
#undef STEPC3
#undef STEPC4

    if (right) {
        // Producer (ranks 1, 3): publish S0 to rank-1, then wait for done.
        if (t == 0) { FENCE_CLUSTER(); mbar_arrive_remote(a_ready, rank - 1); }
        mbar_wait0(a_done);
        return;
    }

    // Consumers (ranks 0, 2): wait for peer's S0, pull it into S1, merge.
    mbar_wait0(a_ready);
    FENCE_CLUSTER();
    {
        float* S1f = (float*)S1;
        uint32_t s0a = smem_u32(S0);
        for (int i = t; i < 972; i += NTH)
            S1f[i] = ld_cluster_f32(s0a + (uint32_t)i * 4u, rank + 1);
    }
    __syncthreads();
    if (t == 0) mbar_arrive_remote(a_done, rank + 1);  // peer may exit

    {
        uint32_t m2a = smem_u32(M2);
        for (int v = t; v < 729; v += NTH) {
            int v1 = v / 27, v2 = v - 27 * (v / 27);
            const float4* L = S0 + v1 * 9;
            const float4* R = S1 + v2 * 9;
            float s = 0.0f;
            #pragma unroll
            for (int j = 0; j < 9; ++j) s += dot3(L[j], R[j]);
            if (bottom) st_cluster_f32(m2a + (uint32_t)v * 4u, 0, s);
            else        M[v] = s;
        }
    }

    if (bottom) {
        // rank 2: signal M2 delivered, exit.
        __syncthreads();
        if (t == 0) { FENCE_CLUSTER(); mbar_arrive_remote(a_m2, 0); }
        return;
    }

    // rank 0: wait for M2, dot, write.
    mbar_wait0(a_m2);
    FENCE_CLUSTER();
    {
        float s = 0.0f;
        for (int v = t; v < 729; v += NTH) s += M[v] * M2[v];
        #pragma unroll
        for (int o = 16; o; o >>= 1) s += __shfl_xor_sync(0xFFFFFFFFu, s, o);
        if ((t & 31) == 0) red[t >> 5] = s;
        __syncthreads();
        if (t == 0) {
            float tt = 0.0f;
            #pragma unroll
            for (int w = 0; w < 8; ++w) tt += red[w];
            out[b] = tt;
        }
    }
}

extern "C" void kernel_launch(void* const* d_in, const int* in_sizes, int n_in,
                              void* d_out, int out_size) {
    const int*   xcfg = nullptr;
    const float* T    = nullptr;
    for (int i = 0; i < n_in; ++i) {
        if (in_sizes[i] == 576) xcfg = (const int*)d_in[i];
        else                    T    = (const float*)d_in[i];
    }
    float* out = (float*)d_out;
    peps_quad_kernel<<<64, NTH>>>(xcfg, T, out);
}